// round 2
// baseline (speedup 1.0000x reference)
#include <cuda_runtime.h>

#define NSEG 128
#define KC   64
#define BZD  64

constexpr int PIX = 8;             // pixels (consecutive j) per thread -> 4 f32x2 pairs
constexpr int THREADS = 64;        // 64-thread blocks: 1024 blocks -> 6.9/SM, tail ~1.01x
constexpr int ROWS_PER_BLOCK = THREADS * PIX / BZD;   // 8 rows
constexpr int TILES_PER_SEG = BZD / ROWS_PER_BLOCK;   // 8
constexpr int NPAIR = PIX / 2;     // 4

typedef unsigned long long u64;

__device__ __forceinline__ float ex2f(float x) {
    float r;
    asm("ex2.approx.ftz.f32 %0, %1;" : "=f"(r) : "f"(x));
    return r;
}
__device__ __forceinline__ u64 pk2(float lo, float hi) {
    u64 r; asm("mov.b64 %0, {%1,%2};" : "=l"(r) : "f"(lo), "f"(hi)); return r;
}
__device__ __forceinline__ void upk2(float& lo, float& hi, u64 v) {
    asm("mov.b64 {%0,%1}, %2;" : "=f"(lo), "=f"(hi) : "l"(v));
}
__device__ __forceinline__ u64 fma2(u64 a, u64 b, u64 c) {
    u64 r; asm("fma.rn.f32x2 %0, %1, %2, %3;" : "=l"(r) : "l"(a), "l"(b), "l"(c)); return r;
}
__device__ __forceinline__ u64 add2(u64 a, u64 b) {
    u64 r; asm("add.rn.f32x2 %0, %1, %2;" : "=l"(r) : "l"(a), "l"(b)); return r;
}

__global__ __launch_bounds__(THREADS)
void seg_splat_kernel(const float* __restrict__ u,
                      const float* __restrict__ a,
                      const float* __restrict__ B,
                      float* __restrict__ out)
{
    // Per-k constants. Pair-replicated entries load straight into packed b64 regs.
    __shared__ float4 sQ[KC];     // {A', Bc', ux, unused}
    __shared__ u64 sC2[KC];       // {C', C'}
    __shared__ u64 sA2[KC];       // {a, a}
    __shared__ u64 sNU2[KC];      // {-uy, -uy}

    const int n    = blockIdx.x / TILES_PER_SEG;
    const int tile = blockIdx.x % TILES_PER_SEG;
    const int tid  = threadIdx.x;

    // One component per thread (THREADS == KC)
    {
        const int k = tid;
        const float* bp = B + (size_t)(n * KC + k) * 4;
        float b00 = bp[0];
        float b10 = bp[2];
        float b11 = bp[3];
        const float L = -0.72134752044448170368f;  // -0.5 * log2(e)
        float A  = L * (b00 * b00 + b10 * b10);
        float Bc = 2.0f * L * (b10 * b11);
        float C  = L * (b11 * b11);
        const float* up = u + (size_t)(n * KC + k) * 2;
        float av = a[n * KC + k];
        sQ[k]   = make_float4(A, Bc, up[0], 0.0f);
        sC2[k]  = pk2(C, C);
        sA2[k]  = pk2(av, av);
        sNU2[k] = pk2(-up[1], -up[1]);
    }
    __syncthreads();

    constexpr int THREADS_PER_ROW = BZD / PIX;  // 8
    const int row = tid / THREADS_PER_ROW;
    const int j0  = (tid % THREADS_PER_ROW) * PIX;
    const int i   = tile * ROWS_PER_BLOCK + row;

    const float xi = ((float)i + 0.5f) * (1.0f / BZD);
    u64 yv2[NPAIR];
#pragma unroll
    for (int p = 0; p < NPAIR; p++) {
        float y0 = ((float)(j0 + 2 * p)     + 0.5f) * (1.0f / BZD);
        float y1 = ((float)(j0 + 2 * p + 1) + 0.5f) * (1.0f / BZD);
        yv2[p] = pk2(y0, y1);
    }

    u64 num2[NPAIR], den2[NPAIR];
    const u64 zz = pk2(0.0f, 0.0f);
#pragma unroll
    for (int p = 0; p < NPAIR; p++) { num2[p] = zz; den2[p] = zz; }

#pragma unroll 4
    for (int k = 0; k < KC; k++) {
        float4 q = sQ[k];
        u64 c2  = sC2[k];
        u64 a2  = sA2[k];
        u64 nu2 = sNU2[k];
        float dx = xi - q.z;
        float P1 = q.y * dx;
        float P0 = (q.x * dx) * dx;
        u64 P1_2 = pk2(P1, P1);
        u64 P0_2 = pk2(P0, P0);
#pragma unroll
        for (int p = 0; p < NPAIR; p++) {
            u64 dy2 = add2(yv2[p], nu2);
            u64 t   = fma2(c2, dy2, P1_2);           // C*dy + B*dx
            u64 e2  = fma2(dy2, t, P0_2);            // A*dx^2 + B*dx*dy + C*dy^2 (log2 scale)
            float e0, e1; upk2(e0, e1, e2);
            u64 kv2 = pk2(ex2f(e0), ex2f(e1));
            den2[p] = add2(den2[p], kv2);
            num2[p] = fma2(a2, kv2, num2[p]);
        }
    }

    float4 o[2];
#pragma unroll
    for (int p = 0; p < NPAIR; p++) {
        float n0, n1, d0, d1;
        upk2(n0, n1, num2[p]);
        upk2(d0, d1, den2[p]);
        float r0 = n0 / fmaxf(d0, 1e-7f);
        float r1 = n1 / fmaxf(d1, 1e-7f);
        ((float*)o)[2 * p]     = r0;
        ((float*)o)[2 * p + 1] = r1;
    }
    float4* op = (float4*)(out + (size_t)n * (BZD * BZD) + (size_t)i * BZD + j0);
    op[0] = o[0];
    op[1] = o[1];
}

extern "C" void kernel_launch(void* const* d_in, const int* in_sizes, int n_in,
                              void* d_out, int out_size)
{
    const float* u = (const float*)d_in[0];
    const float* a = (const float*)d_in[1];
    const float* B = (const float*)d_in[2];
    float* out     = (float*)d_out;

    int blocks = NSEG * TILES_PER_SEG;  // 1024
    seg_splat_kernel<<<blocks, THREADS>>>(u, a, B, out);
}

// round 3
// speedup vs baseline: 1.1654x; 1.1654x over previous
#include <cuda_runtime.h>

#define NSEG 128
#define KC   64
#define BZD  64

constexpr int PIX = 16;                               // consecutive y pixels per thread
constexpr int THREADS = 32;                           // 1 warp per block
constexpr int TPR = BZD / PIX;                        // 4 threads per row
constexpr int ROWS_PER_BLOCK = THREADS / TPR;         // 8
constexpr int TILES_PER_SEG = BZD / ROWS_PER_BLOCK;   // 8
constexpr int NPAIR = PIX / 2;                        // 8

typedef unsigned long long u64;

__device__ __forceinline__ float ex2f(float x) {
    float r; asm("ex2.approx.ftz.f32 %0, %1;" : "=f"(r) : "f"(x)); return r;
}
__device__ __forceinline__ u64 pk2(float lo, float hi) {
    u64 r; asm("mov.b64 %0, {%1,%2};" : "=l"(r) : "f"(lo), "f"(hi)); return r;
}
__device__ __forceinline__ void upk2(float& lo, float& hi, u64 v) {
    asm("mov.b64 {%0,%1}, %2;" : "=f"(lo), "=f"(hi) : "l"(v));
}
__device__ __forceinline__ u64 fma2(u64 a, u64 b, u64 c) {
    u64 r; asm("fma.rn.f32x2 %0, %1, %2, %3;" : "=l"(r) : "l"(a), "l"(b), "l"(c)); return r;
}
__device__ __forceinline__ u64 add2(u64 a, u64 b) {
    u64 r; asm("add.rn.f32x2 %0, %1, %2;" : "=l"(r) : "l"(a), "l"(b)); return r;
}
__device__ __forceinline__ u64 mul2(u64 a, u64 b) {
    u64 r; asm("mul.rn.f32x2 %0, %1, %2;" : "=l"(r) : "l"(a), "l"(b)); return r;
}

__global__ __launch_bounds__(THREADS)
void seg_splat_kernel(const float* __restrict__ u,
                      const float* __restrict__ a,
                      const float* __restrict__ B,
                      float* __restrict__ out)
{
    __shared__ float4 sK1[KC];   // {A', Bc', ux, uy}
    __shared__ float4 sK2[KC];   // {C', 2C'h, gamma, s2}
    __shared__ float2 sK3[KC];   // {s4, a}
    __shared__ u64    sS8[KC];   // {s8, s8}

    const int n    = blockIdx.x / TILES_PER_SEG;
    const int tile = blockIdx.x % TILES_PER_SEG;
    const int tid  = threadIdx.x;

    const float h = 1.0f / BZD;

    // Per-component constants (2 components per thread)
    for (int k = tid; k < KC; k += THREADS) {
        const float* bp = B + (size_t)(n * KC + k) * 4;
        float b00 = bp[0], b10 = bp[2], b11 = bp[3];
        const float L = -0.72134752044448170368f;   // -0.5 * log2(e)
        float A  = L * (b00 * b00 + b10 * b10);
        float Bc = 2.0f * L * (b10 * b11);
        float C  = L * (b11 * b11);
        float gamma = C * (h * h);                  // per-k quadratic step (log2 domain)
        float s2 = ex2f(2.0f * gamma);
        float s4 = s2 * s2;
        float s8 = s4 * s4;
        const float* up = u + (size_t)(n * KC + k) * 2;
        float av = a[n * KC + k];
        sK1[k] = make_float4(A, Bc, up[0], up[1]);
        sK2[k] = make_float4(C, 2.0f * C * h, gamma, s2);
        sK3[k] = make_float2(s4, av);
        sS8[k] = pk2(s8, s8);
    }
    __syncthreads();

    const int row = tid / TPR;
    const int j0  = (tid % TPR) * PIX;
    const int i   = tile * ROWS_PER_BLOCK + row;

    const float xi = ((float)i  + 0.5f) * h;
    const float y0 = ((float)j0 + 0.5f) * h;

    u64 num2[NPAIR], den2[NPAIR];
    const u64 zz = pk2(0.0f, 0.0f);
#pragma unroll
    for (int p = 0; p < NPAIR; p++) { num2[p] = zz; den2[p] = zz; }

#pragma unroll 2
    for (int k = 0; k < KC; k++) {
        float4 k1 = sK1[k];
        float4 k2 = sK2[k];
        float2 k3 = sK3[k];
        u64  s8_2 = sS8[k];

        float dx  = xi - k1.z;
        float dy0 = y0 - k1.w;
        float bdx = k1.y * dx;                       // Bc'*dx
        float adx = k1.x * dx;                       // A'*dx
        float t3  = fmaf(k2.x, dy0, bdx);            // C'*dy0 + Bc'*dx
        float E0  = fmaf(dy0, t3, adx * dx);         // quadratic form at t=0 (log2)
        float beta = fmaf(k2.y, dy0, bdx * h);       // h*(Bc'dx + 2C'dy0)
        float bpg = beta + k2.z;                     // beta + gamma

        float kv0 = ex2f(E0);                        // kernel at pixel t=0
        float w   = ex2f(bpg);                       // 2^(beta+gamma)
        float kv1 = kv0 * w;                         // pixel t=1
        float w2  = w * w;
        float rlo = w2 * k2.w;                       // 2^(2b+4g): even-lane stride-2 ratio
        float rhi = rlo * k3.x;                      // 2^(2b+8g): odd-lane ratio

        u64 kv2 = pk2(kv0, kv1);
        u64 r2  = pk2(rlo, rhi);
        u64 a2  = pk2(k3.y, k3.y);

#pragma unroll
        for (int p = 0; p < NPAIR; p++) {
            den2[p] = add2(den2[p], kv2);
            num2[p] = fma2(a2, kv2, num2[p]);
            if (p < NPAIR - 1) {
                kv2 = mul2(kv2, r2);                 // advance both lanes by 2 pixels
                r2  = mul2(r2, s8_2);                // quadratic ratio update
            }
        }
    }

    float res[PIX];
#pragma unroll
    for (int p = 0; p < NPAIR; p++) {
        float n0, n1, d0, d1;
        upk2(n0, n1, num2[p]);
        upk2(d0, d1, den2[p]);
        res[2 * p]     = n0 / fmaxf(d0, 1e-7f);
        res[2 * p + 1] = n1 / fmaxf(d1, 1e-7f);
    }

    float4* op = (float4*)(out + (size_t)n * (BZD * BZD) + (size_t)i * BZD + j0);
#pragma unroll
    for (int q = 0; q < PIX / 4; q++)
        op[q] = ((float4*)res)[q];
}

extern "C" void kernel_launch(void* const* d_in, const int* in_sizes, int n_in,
                              void* d_out, int out_size)
{
    const float* u = (const float*)d_in[0];
    const float* a = (const float*)d_in[1];
    const float* B = (const float*)d_in[2];
    float* out     = (float*)d_out;

    int blocks = NSEG * TILES_PER_SEG;   // 1024 one-warp blocks
    seg_splat_kernel<<<blocks, THREADS>>>(u, a, B, out);
}